// round 2
// baseline (speedup 1.0000x reference)
#include <cuda_runtime.h>
#include <math.h>

#define DIM   768
#define NH    12
#define HD    64
#define HID   3072
#define BATCH 4
#define SEQ   2048
#define NT    (BATCH*SEQ)   /* 8192 tokens */
#define NBH   (BATCH*NH)    /* 48 (b,h) pairs */
#define ATTN_SCALE 0.125f   /* 64^-0.5 */

/* ---------------- scratch (device globals; no allocs allowed) ------------- */
__device__ float g_h   [(size_t)NT * DIM];        /* LN1 out            */
__device__ float g_qkv [(size_t)NT * 3 * DIM];    /* qkv                */
__device__ float g_sc  [(size_t)NBH * SEQ * SEQ]; /* attention scores   */
__device__ float g_attn[(size_t)NT * DIM];        /* attn output        */
__device__ float g_x1  [(size_t)NT * DIM];        /* x + proj           */
__device__ float g_h2  [(size_t)NT * DIM];        /* LN2 out            */
__device__ float g_act [(size_t)NT * HID];        /* gelu(ffn1)         */

/* ---------------- layernorm ---------------------------------------------- */
__global__ __launch_bounds__(256) void ln_kernel(
    const float* __restrict__ x, const float* __restrict__ gamma,
    const float* __restrict__ beta, float* __restrict__ out)
{
    int row = blockIdx.x;
    const float* xr = x + (size_t)row * DIM;
    float s = 0.f, s2 = 0.f;
    for (int i = threadIdx.x; i < DIM; i += 256) {
        float v = xr[i]; s += v; s2 += v * v;
    }
    __shared__ float sh[64];
    #pragma unroll
    for (int o = 16; o > 0; o >>= 1) {
        s  += __shfl_xor_sync(0xffffffffu, s,  o);
        s2 += __shfl_xor_sync(0xffffffffu, s2, o);
    }
    int warp = threadIdx.x >> 5, lane = threadIdx.x & 31;
    if (lane == 0) { sh[warp] = s; sh[warp + 32] = s2; }
    __syncthreads();
    if (threadIdx.x < 32) {
        s  = (threadIdx.x < 8) ? sh[threadIdx.x]      : 0.f;
        s2 = (threadIdx.x < 8) ? sh[threadIdx.x + 32] : 0.f;
        #pragma unroll
        for (int o = 4; o > 0; o >>= 1) {
            s  += __shfl_xor_sync(0xffffffffu, s,  o);
            s2 += __shfl_xor_sync(0xffffffffu, s2, o);
        }
        if (lane == 0) { sh[0] = s; sh[1] = s2; }
    }
    __syncthreads();
    float mu  = sh[0] * (1.f / DIM);
    float var = sh[1] * (1.f / DIM) - mu * mu;
    float inv = rsqrtf(var + 1e-6f);
    float* orow = out + (size_t)row * DIM;
    for (int i = threadIdx.x; i < DIM; i += 256)
        orow[i] = (xr[i] - mu) * inv * gamma[i] + beta[i];
}

/* ---------------- softmax over rows of 2048 ------------------------------ */
__global__ __launch_bounds__(256) void softmax_kernel(float* __restrict__ scores)
{
    float* p = scores + (size_t)blockIdx.x * SEQ;
    float v[8];
    float mx = -1e30f;
    #pragma unroll
    for (int j = 0; j < 8; j++) {
        v[j] = p[threadIdx.x + 256 * j];
        mx = fmaxf(mx, v[j]);
    }
    __shared__ float sh[8];
    #pragma unroll
    for (int o = 16; o > 0; o >>= 1) mx = fmaxf(mx, __shfl_xor_sync(0xffffffffu, mx, o));
    int warp = threadIdx.x >> 5, lane = threadIdx.x & 31;
    if (lane == 0) sh[warp] = mx;
    __syncthreads();
    mx = fmaxf(fmaxf(fmaxf(sh[0], sh[1]), fmaxf(sh[2], sh[3])),
               fmaxf(fmaxf(sh[4], sh[5]), fmaxf(sh[6], sh[7])));
    float sum = 0.f;
    #pragma unroll
    for (int j = 0; j < 8; j++) { v[j] = __expf(v[j] - mx); sum += v[j]; }
    #pragma unroll
    for (int o = 16; o > 0; o >>= 1) sum += __shfl_xor_sync(0xffffffffu, sum, o);
    __syncthreads();
    if (lane == 0) sh[warp] = sum;
    __syncthreads();
    sum = sh[0] + sh[1] + sh[2] + sh[3] + sh[4] + sh[5] + sh[6] + sh[7];
    float inv = 1.f / sum;
    #pragma unroll
    for (int j = 0; j < 8; j++) p[threadIdx.x + 256 * j] = v[j] * inv;
}

/* ---------------- generic tiled SGEMM (NN), fused epilogue ---------------- */
/* C[M,N] = A[M,K] @ B[K,N] (+bias) (gelu) (+resid). 64x64 tile, BK=16,
   256 threads, 4x4 register micro-tile. M,N % 64 == 0, K % 16 == 0. */
template<bool BIAS, bool RESID, bool GELU>
__global__ __launch_bounds__(256) void gemm_nn(
    const float* __restrict__ A, int lda,
    const float* __restrict__ B, int ldb,
    const float* __restrict__ bias,
    const float* __restrict__ resid, int ldr,
    float* __restrict__ C, int ldc,
    int M, int N, int K)
{
    __shared__ __align__(16) float As[16][64];
    __shared__ __align__(16) float Bs[16][64];
    const int tid = threadIdx.x;
    const int tx = tid & 15, ty = tid >> 4;
    const int m0 = blockIdx.y * 64, n0 = blockIdx.x * 64;
    const int arow = tid >> 2, akc = (tid & 3) << 2;
    const int brow = tid >> 4, bnc = (tid & 15) << 2;
    const float* aptr = A + (size_t)(m0 + arow) * lda + akc;
    const float* bptr = B + (size_t)brow * ldb + n0 + bnc;
    float acc[4][4] = {};
    for (int k0 = 0; k0 < K; k0 += 16) {
        float4 av = *(const float4*)(aptr + k0);
        float4 bv = *(const float4*)(bptr + (size_t)k0 * ldb);
        __syncthreads();
        As[akc + 0][arow] = av.x; As[akc + 1][arow] = av.y;
        As[akc + 2][arow] = av.z; As[akc + 3][arow] = av.w;
        *(float4*)&Bs[brow][bnc] = bv;
        __syncthreads();
        #pragma unroll
        for (int k = 0; k < 16; k++) {
            float4 a = *(const float4*)&As[k][ty << 2];
            float4 b = *(const float4*)&Bs[k][tx << 2];
            acc[0][0] += a.x*b.x; acc[0][1] += a.x*b.y; acc[0][2] += a.x*b.z; acc[0][3] += a.x*b.w;
            acc[1][0] += a.y*b.x; acc[1][1] += a.y*b.y; acc[1][2] += a.y*b.z; acc[1][3] += a.y*b.w;
            acc[2][0] += a.z*b.x; acc[2][1] += a.z*b.y; acc[2][2] += a.z*b.z; acc[2][3] += a.z*b.w;
            acc[3][0] += a.w*b.x; acc[3][1] += a.w*b.y; acc[3][2] += a.w*b.z; acc[3][3] += a.w*b.w;
        }
    }
    #pragma unroll
    for (int i = 0; i < 4; i++) {
        int m = m0 + (ty << 2) + i;
        #pragma unroll
        for (int j = 0; j < 4; j++) {
            int n = n0 + (tx << 2) + j;
            float v = acc[i][j];
            if (BIAS)  v += bias[n];
            if (GELU)  v = 0.5f * v * (1.f + erff(v * 0.7071067811865476f));
            if (RESID) v += resid[(size_t)m * ldr + n];
            C[(size_t)m * ldc + n] = v;
        }
    }
}

/* ---------------- scores = scale * Q K^T, masked (batched NT GEMM) -------- */
__global__ __launch_bounds__(256) void attn_scores_kernel(
    const float* __restrict__ qkv, const int* __restrict__ mask,
    float* __restrict__ scores)
{
    const int z = blockIdx.z, b = z / NH, h = z % NH;
    const float* Aq = qkv + (size_t)b * SEQ * (3 * DIM) + h * HD;        /* Q */
    const float* Bk = qkv + (size_t)b * SEQ * (3 * DIM) + DIM + h * HD;  /* K */
    const int*   mb = mask + (size_t)b * SEQ * SEQ;
    float*       C  = scores + (size_t)z * SEQ * SEQ;

    __shared__ __align__(16) float As[16][64];
    __shared__ __align__(16) float Bs[16][64];
    const int tid = threadIdx.x;
    const int tx = tid & 15, ty = tid >> 4;
    const int m0 = blockIdx.y * 64, n0 = blockIdx.x * 64;
    const int row = tid >> 2, kc = (tid & 3) << 2;
    float acc[4][4] = {};
    #pragma unroll
    for (int k0 = 0; k0 < HD; k0 += 16) {
        float4 av = *(const float4*)(Aq + (size_t)(m0 + row) * (3 * DIM) + k0 + kc);
        float4 bv = *(const float4*)(Bk + (size_t)(n0 + row) * (3 * DIM) + k0 + kc);
        __syncthreads();
        As[kc + 0][row] = av.x; As[kc + 1][row] = av.y; As[kc + 2][row] = av.z; As[kc + 3][row] = av.w;
        Bs[kc + 0][row] = bv.x; Bs[kc + 1][row] = bv.y; Bs[kc + 2][row] = bv.z; Bs[kc + 3][row] = bv.w;
        __syncthreads();
        #pragma unroll
        for (int k = 0; k < 16; k++) {
            float4 a = *(const float4*)&As[k][ty << 2];
            float4 b2 = *(const float4*)&Bs[k][tx << 2];
            acc[0][0] += a.x*b2.x; acc[0][1] += a.x*b2.y; acc[0][2] += a.x*b2.z; acc[0][3] += a.x*b2.w;
            acc[1][0] += a.y*b2.x; acc[1][1] += a.y*b2.y; acc[1][2] += a.y*b2.z; acc[1][3] += a.y*b2.w;
            acc[2][0] += a.z*b2.x; acc[2][1] += a.z*b2.y; acc[2][2] += a.z*b2.z; acc[2][3] += a.z*b2.w;
            acc[3][0] += a.w*b2.x; acc[3][1] += a.w*b2.y; acc[3][2] += a.w*b2.z; acc[3][3] += a.w*b2.w;
        }
    }
    #pragma unroll
    for (int i = 0; i < 4; i++) {
        int m = m0 + (ty << 2) + i;
        #pragma unroll
        for (int j = 0; j < 4; j++) {
            int n = n0 + (tx << 2) + j;
            int mv = mb[(size_t)m * SEQ + n];
            C[(size_t)m * SEQ + n] = mv ? acc[i][j] * ATTN_SCALE : -10000.f;
        }
    }
}

/* ---------------- attn_out = P @ V (batched NN GEMM, N=64) ---------------- */
__global__ __launch_bounds__(256) void attn_av_kernel(
    const float* __restrict__ scores, const float* __restrict__ qkv,
    float* __restrict__ attn)
{
    const int z = blockIdx.z, b = z / NH, h = z % NH;
    const float* A = scores + (size_t)z * SEQ * SEQ;                         /* lda SEQ   */
    const float* B = qkv + (size_t)b * SEQ * (3 * DIM) + 2 * DIM + h * HD;   /* ldb 2304  */
    float*       C = attn + (size_t)b * SEQ * DIM + h * HD;                  /* ldc 768   */

    __shared__ __align__(16) float As[16][64];
    __shared__ __align__(16) float Bs[16][64];
    const int tid = threadIdx.x;
    const int tx = tid & 15, ty = tid >> 4;
    const int m0 = blockIdx.y * 64;
    const int arow = tid >> 2, akc = (tid & 3) << 2;
    const int brow = tid >> 4, bnc = (tid & 15) << 2;
    float acc[4][4] = {};
    for (int k0 = 0; k0 < SEQ; k0 += 16) {
        float4 av = *(const float4*)(A + (size_t)(m0 + arow) * SEQ + k0 + akc);
        float4 bv = *(const float4*)(B + (size_t)(k0 + brow) * (3 * DIM) + bnc);
        __syncthreads();
        As[akc + 0][arow] = av.x; As[akc + 1][arow] = av.y;
        As[akc + 2][arow] = av.z; As[akc + 3][arow] = av.w;
        *(float4*)&Bs[brow][bnc] = bv;
        __syncthreads();
        #pragma unroll
        for (int k = 0; k < 16; k++) {
            float4 a = *(const float4*)&As[k][ty << 2];
            float4 b2 = *(const float4*)&Bs[k][tx << 2];
            acc[0][0] += a.x*b2.x; acc[0][1] += a.x*b2.y; acc[0][2] += a.x*b2.z; acc[0][3] += a.x*b2.w;
            acc[1][0] += a.y*b2.x; acc[1][1] += a.y*b2.y; acc[1][2] += a.y*b2.z; acc[1][3] += a.y*b2.w;
            acc[2][0] += a.z*b2.x; acc[2][1] += a.z*b2.y; acc[2][2] += a.z*b2.z; acc[2][3] += a.z*b2.w;
            acc[3][0] += a.w*b2.x; acc[3][1] += a.w*b2.y; acc[3][2] += a.w*b2.z; acc[3][3] += a.w*b2.w;
        }
    }
    #pragma unroll
    for (int i = 0; i < 4; i++) {
        int m = m0 + (ty << 2) + i;
        #pragma unroll
        for (int j = 0; j < 4; j++) {
            int n = (tx << 2) + j;
            C[(size_t)m * DIM + n] = acc[i][j];
        }
    }
}

/* ---------------- driver --------------------------------------------------- */
extern "C" void kernel_launch(void* const* d_in, const int* in_sizes, int n_in,
                              void* d_out, int out_size)
{
    const float* x      = (const float*)d_in[0];
    const int*   mask   = (const int*)  d_in[1];
    const float* w_qkv  = (const float*)d_in[2];
    const float* b_qkv  = (const float*)d_in[3];
    const float* w_proj = (const float*)d_in[4];
    const float* b_proj = (const float*)d_in[5];
    const float* g1     = (const float*)d_in[6];
    const float* beta1  = (const float*)d_in[7];
    const float* g2     = (const float*)d_in[8];
    const float* beta2  = (const float*)d_in[9];
    const float* w1     = (const float*)d_in[10];
    const float* b1     = (const float*)d_in[11];
    const float* w2     = (const float*)d_in[12];
    const float* b2     = (const float*)d_in[13];
    float* out = (float*)d_out;

    float *ph, *pqkv, *psc, *pattn, *px1, *ph2, *pact;
    cudaGetSymbolAddress((void**)&ph,    g_h);
    cudaGetSymbolAddress((void**)&pqkv,  g_qkv);
    cudaGetSymbolAddress((void**)&psc,   g_sc);
    cudaGetSymbolAddress((void**)&pattn, g_attn);
    cudaGetSymbolAddress((void**)&px1,   g_x1);
    cudaGetSymbolAddress((void**)&ph2,   g_h2);
    cudaGetSymbolAddress((void**)&pact,  g_act);

    /* 1. h = LN(x) */
    ln_kernel<<<NT, 256>>>(x, g1, beta1, ph);
    /* 2. qkv = h @ w_qkv + b_qkv   (8192 x 2304 x 768) */
    gemm_nn<true, false, false><<<dim3(36, 128, 1), 256>>>(
        ph, DIM, w_qkv, 3 * DIM, b_qkv, nullptr, 0, pqkv, 3 * DIM, NT, 3 * DIM, DIM);
    /* 3. scores = mask(scale * Q K^T) */
    attn_scores_kernel<<<dim3(32, 32, NBH), 256>>>(pqkv, mask, psc);
    /* 4. softmax rows */
    softmax_kernel<<<NBH * SEQ, 256>>>(psc);
    /* 5. attn = P @ V */
    attn_av_kernel<<<dim3(1, 32, NBH), 256>>>(psc, pqkv, pattn);
    /* 6. x1 = x + attn @ w_proj + b_proj */
    gemm_nn<true, true, false><<<dim3(12, 128, 1), 256>>>(
        pattn, DIM, w_proj, DIM, b_proj, x, DIM, px1, DIM, NT, DIM, DIM);
    /* 7. h2 = LN(x1) */
    ln_kernel<<<NT, 256>>>(px1, g2, beta2, ph2);
    /* 8. act = gelu(h2 @ w1 + b1)   (8192 x 3072 x 768) */
    gemm_nn<true, false, true><<<dim3(48, 128, 1), 256>>>(
        ph2, DIM, w1, HID, b1, nullptr, 0, pact, HID, NT, HID, DIM);
    /* 9. out = x1 + act @ w2 + b2   (8192 x 768 x 3072) */
    gemm_nn<true, true, false><<<dim3(12, 128, 1), 256>>>(
        pact, HID, w2, DIM, b2, px1, DIM, out, DIM, NT, DIM, HID);
}